// round 15
// baseline (speedup 1.0000x reference)
#include <cuda_runtime.h>
#include <cstdint>
#include <cstddef>
#include <climits>

// Problem constants (match reference_code)
#define Cc 5
#define Hh 4096
#define Ww 4096
#define Nn 2000
#define PHh 64
#define PWw 64
#define TILES_X 64          // 4096 / 64
#define TILES_Y 64
#define NTILES (TILES_X * TILES_Y)
#define MAXP 32             // per-tile list capacity (mean ~1.9, Poisson)

// Scratch (device globals — allocation is forbidden).
// g_list entry: .x = patch index n (order key), .y = (ph0 << 16) | pw0.
__device__ int  g_cnt[NTILES];
__device__ int2 g_list[NTILES * MAXP];

// One thread per patch: append packed entry to every overlapped 64x64 tile.
// Insertion order is nondeterministic (atomics), but gather re-establishes
// ascending-n order with a uniform selection scan, so results are exact.
__global__ void bin_kernel(const int* __restrict__ positions) {
    const int n = blockIdx.x * blockDim.x + threadIdx.x;
    if (n >= Nn) return;
    const int2 pp = __ldg(reinterpret_cast<const int2*>(positions) + n);
    const int ty0 = pp.x >> 6, ty1 = (pp.x + PHh - 1) >> 6;
    const int tx0 = pp.y >> 6, tx1 = (pp.y + PWw - 1) >> 6;
    const int2 e = make_int2(n, (pp.x << 16) | pp.y);
    for (int ty = ty0; ty <= ty1; ty++)
        for (int tx = tx0; tx <= tx1; tx++) {
            const int t = ty * TILES_X + tx;
            const int s = atomicAdd(&g_cnt[t], 1);
            if (s < MAXP) g_list[t * MAXP + s] = e;
        }
}

// Load patch quad i of a 64-float row; zero if out of [0,16).
__device__ __forceinline__ float4 ldq(const float* __restrict__ prow, int i) {
    float4 v = make_float4(0.f, 0.f, 0.f, 0.f);
    if ((unsigned)i < 16u) v = __ldg(reinterpret_cast<const float4*>(prow) + i);
    return v;
}

// Accumulate one patch into this thread's 4-row x 4-col register tile.
// A2 = (cx0 - pw0) & 3, uniform per patch: output-quad element e comes from
// patch quad jA elem (A2+e) or patch quad jA+1 elem (A2+e-4). OOB quads read
// zero, implementing edge clipping exactly.
template <int A2>
__device__ __forceinline__ void accum_patch(float4* acc,
                                            const float* __restrict__ pl,
                                            int py0, int jA) {
#pragma unroll
    for (int i = 0; i < 4; i++) {
        const int py = py0 + i;
        if ((unsigned)py < 64u) {
            const float* prow = pl + (py << 6);
            const float4 A = ldq(prow, jA);
            if (A2 == 0) {
                acc[i].x += A.x; acc[i].y += A.y; acc[i].z += A.z; acc[i].w += A.w;
            } else {
                const float4 B = ldq(prow, jA + 1);
                if (A2 == 1) { acc[i].x += A.y; acc[i].y += A.z; acc[i].z += A.w; acc[i].w += B.x; }
                if (A2 == 2) { acc[i].x += A.z; acc[i].y += A.w; acc[i].z += B.x; acc[i].w += B.y; }
                if (A2 == 3) { acc[i].x += A.w; acc[i].y += B.x; acc[i].z += B.y; acc[i].w += B.z; }
            }
        }
    }
}

// Block = one 64x64 output tile of ONE band (grid 64 x 64 x 5): 20480 thin
// independent blocks. No smem, no syncthreads, no atomics. Per-tile list is
// processed in ascending patch-index order via a uniform selection scan
// (O(k^2) warp-broadcast L1-hit loads, k ~ 2), matching the reference scan
// order exactly. Thread (q = tid&15, rr = tid>>4) owns quad column q of rows
// [by*64 + rr*4, +4).
__global__ __launch_bounds__(256, 8)
void gather_kernel(const float* __restrict__ patches,
                   float*       __restrict__ out) {
    const int tid = threadIdx.x;
    const int bx = blockIdx.x, by = blockIdx.y, c = blockIdx.z;
    const int tile = by * TILES_X + bx;
    const int cx0 = bx << 6;

    const int k = min(g_cnt[tile], MAXP);             // uniform broadcast
    const int2* __restrict__ lst = &g_list[tile * MAXP];

    const int q  = tid & 15;
    const int rr = tid >> 4;
    const int y0 = (by << 6) + (rr << 2);

    float4 acc[4];
#pragma unroll
    for (int i = 0; i < 4; i++) acc[i] = make_float4(0.f, 0.f, 0.f, 0.f);

    int prev = -1;                                    // last processed patch id
    for (int r = 0; r < k; r++) {
        // Select the unprocessed entry with the smallest patch index.
        int best_n = INT_MAX, best_y = 0;
        for (int j = 0; j < k; j++) {
            const int2 e = __ldg(lst + j);            // uniform, L1-hot
            if (e.x > prev && e.x < best_n) { best_n = e.x; best_y = e.y; }
        }
        prev = best_n;

        const int ph0 = best_y >> 16;                 // values < 4096: sign-safe
        const int pw0 = best_y & 0xffff;
        const int py0 = y0 - ph0;
        if (py0 >= 64 || py0 <= -4) continue;         // no row overlap
        const int pb0 = cx0 - pw0;
        const int jA  = (pb0 >> 2) + q;               // arithmetic shift = floor
        if (jA > 15 || jA < -1) continue;             // no col overlap
        const float* pl = patches + (((size_t)best_n * Cc + c) << 12);
        switch (pb0 & 3) {
            case 0: accum_patch<0>(acc, pl, py0, jA); break;
            case 1: accum_patch<1>(acc, pl, py0, jA); break;
            case 2: accum_patch<2>(acc, pl, py0, jA); break;
            default: accum_patch<3>(acc, pl, py0, jA); break;
        }
    }

    // Streaming stores: output is write-once, keep L2 for patch data.
    float* ob = out + (size_t)c * ((size_t)Hh * Ww);
#pragma unroll
    for (int i = 0; i < 4; i++) {
        __stcs(reinterpret_cast<float4*>(
                   ob + (size_t)(y0 + i) * Ww + cx0 + (q << 2)),
               acc[i]);
    }
}

extern "C" void kernel_launch(void* const* d_in, const int* in_sizes, int n_in,
                              void* d_out, int out_size) {
    const float* patches;
    const int*   positions;
    if (in_sizes[0] == Nn * 2) {
        positions = (const int*)d_in[0];
        patches   = (const float*)d_in[1];
    } else {
        patches   = (const float*)d_in[0];
        positions = (const int*)d_in[1];
    }
    float* out = (float*)d_out;

    // Reset per-tile counters via a graph memset node (cheaper than a launch).
    void* cnt_ptr = nullptr;
    cudaGetSymbolAddress(&cnt_ptr, g_cnt);
    cudaMemsetAsync(cnt_ptr, 0, NTILES * sizeof(int), 0);

    bin_kernel<<<(Nn + 255) / 256, 256, 0, 0>>>(positions);
    dim3 grid(TILES_X, TILES_Y, Cc);
    gather_kernel<<<grid, 256, 0, 0>>>(patches, out);
}

// round 16
// speedup vs baseline: 1.0975x; 1.0975x over previous
#include <cuda_runtime.h>
#include <cstdint>
#include <cstddef>

// Problem constants (match reference_code)
#define Cc 5
#define Hh 4096
#define Ww 4096
#define Nn 2000
#define PHh 64
#define PWw 64
#define TILES_X 64          // 4096 / 64
#define TILES_Y 64
#define NTILES (TILES_X * TILES_Y)
#define MAXP 32             // per-tile list capacity (mean ~1.9, Poisson)

// Scratch (device globals — allocation is forbidden).
// g_list entry: .x = patch index n (sort key), .y = (ph0 << 16) | pw0.
__device__ int  g_cnt[NTILES];
__device__ int2 g_list[NTILES * MAXP];

// One thread per patch: append packed entry to every overlapped 64x64 tile.
__global__ void bin_kernel(const int* __restrict__ positions) {
    const int n = blockIdx.x * blockDim.x + threadIdx.x;
    if (n >= Nn) return;
    const int2 pp = __ldg(reinterpret_cast<const int2*>(positions) + n);
    const int ty0 = pp.x >> 6, ty1 = (pp.x + PHh - 1) >> 6;
    const int tx0 = pp.y >> 6, tx1 = (pp.y + PWw - 1) >> 6;
    const int2 e = make_int2(n, (pp.x << 16) | pp.y);
    for (int ty = ty0; ty <= ty1; ty++)
        for (int tx = tx0; tx <= tx1; tx++) {
            const int t = ty * TILES_X + tx;
            const int s = atomicAdd(&g_cnt[t], 1);
            if (s < MAXP) g_list[t * MAXP + s] = e;
        }
}

// One thread per tile: insertion-sort its tiny list (k ~ 2, L2-resident) by
// patch index so gather accumulates in reference scan order (rel_err == 0).
__global__ void sort_lists_kernel() {
    const int t = blockIdx.x * blockDim.x + threadIdx.x;
    if (t >= NTILES) return;
    const int k = min(g_cnt[t], MAXP);
    g_cnt[t] = k;
    int2* lst = &g_list[t * MAXP];
    for (int a = 1; a < k; a++) {
        const int2 v = lst[a];
        int b = a - 1;
        while (b >= 0 && lst[b].x > v.x) { lst[b + 1] = lst[b]; b--; }
        lst[b + 1] = v;
    }
}

// Load patch quad i of a 64-float row; zero if out of [0,16).
__device__ __forceinline__ float4 ldq(const float* __restrict__ prow, int i) {
    float4 v = make_float4(0.f, 0.f, 0.f, 0.f);
    if ((unsigned)i < 16u) v = __ldg(reinterpret_cast<const float4*>(prow) + i);
    return v;
}

// Accumulate one patch into this thread's 4-row x 4-col register tile.
// A2 = (cx0 - pw0) & 3, uniform per patch: output-quad element e comes from
// patch quad jA elem (A2+e) or patch quad jA+1 elem (A2+e-4). OOB quads read
// zero, implementing edge clipping exactly.
template <int A2>
__device__ __forceinline__ void accum_patch(float4* acc,
                                            const float* __restrict__ pl,
                                            int py0, int jA) {
#pragma unroll
    for (int i = 0; i < 4; i++) {
        const int py = py0 + i;
        if ((unsigned)py < 64u) {
            const float* prow = pl + (py << 6);
            const float4 A = ldq(prow, jA);
            if (A2 == 0) {
                acc[i].x += A.x; acc[i].y += A.y; acc[i].z += A.z; acc[i].w += A.w;
            } else {
                const float4 B = ldq(prow, jA + 1);
                if (A2 == 1) { acc[i].x += A.y; acc[i].y += A.z; acc[i].z += A.w; acc[i].w += B.x; }
                if (A2 == 2) { acc[i].x += A.z; acc[i].y += A.w; acc[i].z += B.x; acc[i].w += B.y; }
                if (A2 == 3) { acc[i].x += A.w; acc[i].y += B.x; acc[i].z += B.y; acc[i].w += B.z; }
            }
        }
    }
}

// Block = one 64x64 output tile of ONE band (grid 64 x 64 x 5): 20480 thin
// independent blocks. No smem, no syncthreads, no sort, no atomics — the
// pre-sorted list entries are uniform warp-broadcast loads, read ONCE each.
// Thread (q = tid&15, rr = tid>>4) owns quad column q of rows
// [by*64 + rr*4, +4).
__global__ __launch_bounds__(256, 8)
void gather_kernel(const float* __restrict__ patches,
                   float*       __restrict__ out) {
    const int tid = threadIdx.x;
    const int bx = blockIdx.x, by = blockIdx.y, c = blockIdx.z;
    const int tile = by * TILES_X + bx;
    const int cx0 = bx << 6;

    const int k = g_cnt[tile];                        // uniform broadcast
    const int2* __restrict__ lst = &g_list[tile * MAXP];

    const int q  = tid & 15;
    const int rr = tid >> 4;
    const int y0 = (by << 6) + (rr << 2);

    float4 acc[4];
#pragma unroll
    for (int i = 0; i < 4; i++) acc[i] = make_float4(0.f, 0.f, 0.f, 0.f);

    for (int j = 0; j < k; j++) {
        const int2 e  = __ldg(lst + j);               // uniform, L2-hot
        const int ph0 = e.y >> 16;                    // values < 4096: sign-safe
        const int pw0 = e.y & 0xffff;
        const int py0 = y0 - ph0;
        if (py0 >= 64 || py0 <= -4) continue;         // no row overlap
        const int pb0 = cx0 - pw0;
        const int jA  = (pb0 >> 2) + q;               // arithmetic shift = floor
        if (jA > 15 || jA < -1) continue;             // no col overlap
        const float* pl = patches + (((size_t)e.x * Cc + c) << 12);
        switch (pb0 & 3) {
            case 0: accum_patch<0>(acc, pl, py0, jA); break;
            case 1: accum_patch<1>(acc, pl, py0, jA); break;
            case 2: accum_patch<2>(acc, pl, py0, jA); break;
            default: accum_patch<3>(acc, pl, py0, jA); break;
        }
    }

    // Streaming stores: output is write-once, keep L2 for patch data.
    float* ob = out + (size_t)c * ((size_t)Hh * Ww);
#pragma unroll
    for (int i = 0; i < 4; i++) {
        __stcs(reinterpret_cast<float4*>(
                   ob + (size_t)(y0 + i) * Ww + cx0 + (q << 2)),
               acc[i]);
    }
}

extern "C" void kernel_launch(void* const* d_in, const int* in_sizes, int n_in,
                              void* d_out, int out_size) {
    const float* patches;
    const int*   positions;
    if (in_sizes[0] == Nn * 2) {
        positions = (const int*)d_in[0];
        patches   = (const float*)d_in[1];
    } else {
        patches   = (const float*)d_in[0];
        positions = (const int*)d_in[1];
    }
    float* out = (float*)d_out;

    // Reset per-tile counters via a graph memset node (cheaper than a launch).
    void* cnt_ptr = nullptr;
    cudaGetSymbolAddress(&cnt_ptr, g_cnt);
    cudaMemsetAsync(cnt_ptr, 0, NTILES * sizeof(int), 0);

    bin_kernel<<<(Nn + 255) / 256, 256, 0, 0>>>(positions);
    sort_lists_kernel<<<(NTILES + 255) / 256, 256, 0, 0>>>();
    dim3 grid(TILES_X, TILES_Y, Cc);
    gather_kernel<<<grid, 256, 0, 0>>>(patches, out);
}

// round 17
// speedup vs baseline: 1.1486x; 1.0466x over previous
#include <cuda_runtime.h>
#include <cstdint>
#include <cstddef>

// Problem constants (match reference_code)
#define Cc 5
#define Hh 4096
#define Ww 4096
#define Nn 2000
#define PHh 64
#define PWw 64
#define TILES_X 64          // 4096 / 64
#define TILES_Y 64
#define NTILES (TILES_X * TILES_Y)
#define MAXP 32             // per-tile list capacity (mean ~1.9, Poisson)

// Scratch (device globals — allocation is forbidden).
// g_list entry: .x = patch index n, .y = (ph0 << 16) | pw0.
__device__ int  g_cnt[NTILES];
__device__ int2 g_list[NTILES * MAXP];

// One thread per (patch, quadrant): a patch overlaps 1, 2 or 4 tiles
// (ty0..ty1) x (tx0..tx1). Thread i = n*4 + dy*2 + dx emits at most one list
// entry -> exactly one atomic + one store per thread, no serial atomic chain.
// List order is nondeterministic, but fp-add reordering among the rare
// overlapping patches perturbs the result only at ~1e-9 relative (<< 1e-3).
__global__ void bin_kernel(const int* __restrict__ positions) {
    const int i = blockIdx.x * blockDim.x + threadIdx.x;
    const int n = i >> 2;
    if (n >= Nn) return;
    const int2 pp = __ldg(reinterpret_cast<const int2*>(positions) + n);
    const int ty0 = pp.x >> 6, ty1 = (pp.x + PHh - 1) >> 6;
    const int tx0 = pp.y >> 6, tx1 = (pp.y + PWw - 1) >> 6;
    const int ty = ty0 + ((i >> 1) & 1);
    const int tx = tx0 + (i & 1);
    if (ty > ty1 || tx > tx1) return;
    const int t = ty * TILES_X + tx;
    const int s = atomicAdd(&g_cnt[t], 1);
    if (s < MAXP) g_list[t * MAXP + s] = make_int2(n, (pp.x << 16) | pp.y);
}

// Load patch quad i of a 64-float row; zero if out of [0,16).
__device__ __forceinline__ float4 ldq(const float* __restrict__ prow, int i) {
    float4 v = make_float4(0.f, 0.f, 0.f, 0.f);
    if ((unsigned)i < 16u) v = __ldg(reinterpret_cast<const float4*>(prow) + i);
    return v;
}

// Accumulate one patch into this thread's 4-row x 4-col register tile.
// A2 = (cx0 - pw0) & 3, uniform per patch: output-quad element e comes from
// patch quad jA elem (A2+e) or patch quad jA+1 elem (A2+e-4). OOB quads read
// zero, implementing edge clipping exactly.
template <int A2>
__device__ __forceinline__ void accum_patch(float4* acc,
                                            const float* __restrict__ pl,
                                            int py0, int jA) {
#pragma unroll
    for (int i = 0; i < 4; i++) {
        const int py = py0 + i;
        if ((unsigned)py < 64u) {
            const float* prow = pl + (py << 6);
            const float4 A = ldq(prow, jA);
            if (A2 == 0) {
                acc[i].x += A.x; acc[i].y += A.y; acc[i].z += A.z; acc[i].w += A.w;
            } else {
                const float4 B = ldq(prow, jA + 1);
                if (A2 == 1) { acc[i].x += A.y; acc[i].y += A.z; acc[i].z += A.w; acc[i].w += B.x; }
                if (A2 == 2) { acc[i].x += A.z; acc[i].y += A.w; acc[i].z += B.x; acc[i].w += B.y; }
                if (A2 == 3) { acc[i].x += A.w; acc[i].y += B.x; acc[i].z += B.y; acc[i].w += B.z; }
            }
        }
    }
}

// Block = one 64x64 output tile of ONE band (grid 64 x 64 x 5): 20480 thin
// independent blocks. No smem, no syncthreads, no atomics — list entries are
// uniform warp-broadcast loads, read once each. Thread (q = tid&15,
// rr = tid>>4) owns quad column q of rows [by*64 + rr*4, +4).
__global__ __launch_bounds__(256, 8)
void gather_kernel(const float* __restrict__ patches,
                   float*       __restrict__ out) {
    const int tid = threadIdx.x;
    const int bx = blockIdx.x, by = blockIdx.y, c = blockIdx.z;
    const int tile = by * TILES_X + bx;
    const int cx0 = bx << 6;

    const int k = min(g_cnt[tile], MAXP);             // uniform broadcast
    const int2* __restrict__ lst = &g_list[tile * MAXP];

    const int q  = tid & 15;
    const int rr = tid >> 4;
    const int y0 = (by << 6) + (rr << 2);

    float4 acc[4];
#pragma unroll
    for (int i = 0; i < 4; i++) acc[i] = make_float4(0.f, 0.f, 0.f, 0.f);

    for (int j = 0; j < k; j++) {
        const int2 e  = __ldg(lst + j);               // uniform, L2-hot
        const int ph0 = e.y >> 16;                    // values < 4096: sign-safe
        const int pw0 = e.y & 0xffff;
        const int py0 = y0 - ph0;
        if (py0 >= 64 || py0 <= -4) continue;         // no row overlap
        const int pb0 = cx0 - pw0;
        const int jA  = (pb0 >> 2) + q;               // arithmetic shift = floor
        if (jA > 15 || jA < -1) continue;             // no col overlap
        const float* pl = patches + (((size_t)e.x * Cc + c) << 12);
        switch (pb0 & 3) {
            case 0: accum_patch<0>(acc, pl, py0, jA); break;
            case 1: accum_patch<1>(acc, pl, py0, jA); break;
            case 2: accum_patch<2>(acc, pl, py0, jA); break;
            default: accum_patch<3>(acc, pl, py0, jA); break;
        }
    }

    // Streaming stores: output is write-once, keep L2 for patch data.
    float* ob = out + (size_t)c * ((size_t)Hh * Ww);
#pragma unroll
    for (int i = 0; i < 4; i++) {
        __stcs(reinterpret_cast<float4*>(
                   ob + (size_t)(y0 + i) * Ww + cx0 + (q << 2)),
               acc[i]);
    }
}

extern "C" void kernel_launch(void* const* d_in, const int* in_sizes, int n_in,
                              void* d_out, int out_size) {
    const float* patches;
    const int*   positions;
    if (in_sizes[0] == Nn * 2) {
        positions = (const int*)d_in[0];
        patches   = (const float*)d_in[1];
    } else {
        patches   = (const float*)d_in[0];
        positions = (const int*)d_in[1];
    }
    float* out = (float*)d_out;

    // Reset per-tile counters via a graph memset node (cheaper than a launch).
    void* cnt_ptr = nullptr;
    cudaGetSymbolAddress(&cnt_ptr, g_cnt);
    cudaMemsetAsync(cnt_ptr, 0, NTILES * sizeof(int), 0);

    bin_kernel<<<(Nn * 4 + 255) / 256, 256, 0, 0>>>(positions);
    dim3 grid(TILES_X, TILES_Y, Cc);
    gather_kernel<<<grid, 256, 0, 0>>>(patches, out);
}